// round 8
// baseline (speedup 1.0000x reference)
#include <cuda_runtime.h>
#include <cuda_fp16.h>
#include <cstdint>

#define DIM     128
#define NMAX    100000
#define MAXDEG  128
#define TILE_M  128
#define SPAD    40          // smem row stride in halfs (32 data + 8 pad = 80B)

// ---------------------------------------------------------------------------
// Scratch (allocation-free rule: module-scope device arrays)
// ---------------------------------------------------------------------------
__device__ int    g_deg[NMAX];                         // zeroed by gemm tail
__device__ int    g_bucket[(size_t)NMAX * MAXDEG];     // 51.2 MB
__device__ __half g_xh[(size_t)NMAX * DIM];            // 25.6 MB  x in fp16
__device__ __half g_yh[(size_t)(NMAX + TILE_M) * DIM]; // fp16 y (zero pad tail)
__device__ __half g_Wh[DIM * DIM];                     // W in fp16
__device__ float  g_beta[NMAX];

__device__ __forceinline__ uint32_t smem_u32(const void* p) {
    uint32_t a;
    asm("{ .reg .u64 t; cvta.to.shared.u64 t, %1; cvt.u32.u64 %0, t; }"
        : "=r"(a) : "l"(p));
    return a;
}

// ---------------------------------------------------------------------------
// K0: fused prep — fill (degree count + bucket scatter) + x->fp16 + W->fp16.
// g_deg is already zero: statically at load, then re-zeroed by gemm's tail
// each replay, so fill can run in the same launch as the converters.
// Blocks [0, convBlocks) do conversions; [convBlocks, +fillBlocks) do fill.
// ---------------------------------------------------------------------------
__global__ void prep_kernel(const float* __restrict__ x,
                            const float* __restrict__ W,
                            const int* __restrict__ ei,
                            int n, int e, int convBlocks) {
    if ((int)blockIdx.x < convBlocks) {
        size_t i = (size_t)blockIdx.x * blockDim.x + threadIdx.x;
        size_t total = (size_t)n * (DIM / 2);
        if (i < total) {
            float2 v = ((const float2*)x)[i];
            ((__half2*)g_xh)[i] = __float22half2_rn(v);
        }
        if (i < DIM * DIM / 2) {
            float2 v = ((const float2*)W)[i];
            ((__half2*)g_Wh)[i] = __float22half2_rn(v);
        }
    } else {
        int i = (blockIdx.x - convBlocks) * blockDim.x + threadIdx.x;
        if (i >= e) return;
        int row = ei[i];
        int col = ei[(size_t)e + i];
        if ((unsigned)row >= (unsigned)n) return;
        if ((unsigned)col >= (unsigned)n) return;
        int slot = atomicAdd(&g_deg[row], 1);
        if (slot < MAXDEG) g_bucket[(size_t)row * MAXDEG + slot] = col;
    }
}

// ---------------------------------------------------------------------------
// K1: warp-per-row aggregation (unchanged from R6/R7)
// y[r] = d_r * sum_c d_c * x[c] + d_r^2 * x[r];  beta[r] = d_r*sum d_c + d_r^2
// ---------------------------------------------------------------------------
__global__ void agg_kernel(int n) {
    int gw   = (blockIdx.x * blockDim.x + threadIdx.x) >> 5;
    int lane = threadIdx.x & 31;
    if (gw >= n) return;

    int degr = g_deg[gw];
    int degc = min(degr, MAXDEG);
    int half = lane >> 4;
    int li   = lane & 15;

    float acc[8];
#pragma unroll
    for (int t = 0; t < 8; t++) acc[t] = 0.f;
    float s = 0.f;

    for (int base = 0; base < degc; base += 32) {
        int m = min(32, degc - base);
        int   c  = 0;
        float dc = 0.f;
        if (lane < m) {
            c  = g_bucket[(size_t)gw * MAXDEG + base + lane];
            dc = rsqrtf((float)max(g_deg[c], 1));
        }
#pragma unroll 4
        for (int j = 0; j < m; j += 2) {
            int idx = j + half;
            int   cj  = __shfl_sync(0xffffffffu, c, idx);
            float dcj = __shfl_sync(0xffffffffu, dc, idx);
            uint4 v = *(const uint4*)(g_xh + (size_t)cj * DIM + li * 8);
            const __half2* hp = (const __half2*)&v;
#pragma unroll
            for (int t = 0; t < 4; t++) {
                float2 f = __half22float2(hp[t]);
                acc[t * 2 + 0] += dcj * f.x;
                acc[t * 2 + 1] += dcj * f.y;
            }
            s += dcj;
        }
    }

#pragma unroll
    for (int t = 0; t < 8; t++)
        acc[t] += __shfl_down_sync(0xffffffffu, acc[t], 16);
    s += __shfl_down_sync(0xffffffffu, s, 16);

    float dr = rsqrtf((float)max(degr, 1));
    float d2 = dr * dr;

    if (lane < 16) {
        uint4 xv = *(const uint4*)(g_xh + (size_t)gw * DIM + li * 8);
        const __half2* xp = (const __half2*)&xv;
        uint4 yo;
        uint32_t* yw = (uint32_t*)&yo;
#pragma unroll
        for (int t = 0; t < 4; t++) {
            float2 xf = __half22float2(xp[t]);
            __half2 p = __float22half2_rn(
                make_float2(dr * acc[t * 2 + 0] + d2 * xf.x,
                            dr * acc[t * 2 + 1] + d2 * xf.y));
            yw[t] = *(const uint32_t*)&p;
        }
        *(uint4*)(g_yh + (size_t)gw * DIM + li * 8) = yo;
    }
    if (lane == 0) g_beta[gw] = dr * s + d2;
}

// ---------------------------------------------------------------------------
// mma.sync m16n8k16 fp16 -> fp32
// ---------------------------------------------------------------------------
__device__ __forceinline__ void mma16816(float c[4],
                                         uint32_t a0, uint32_t a1,
                                         uint32_t a2, uint32_t a3,
                                         uint32_t b0, uint32_t b1) {
    asm volatile(
        "mma.sync.aligned.m16n8k16.row.col.f32.f16.f16.f32 "
        "{%0,%1,%2,%3}, {%4,%5,%6,%7}, {%8,%9}, {%0,%1,%2,%3};"
        : "+f"(c[0]), "+f"(c[1]), "+f"(c[2]), "+f"(c[3])
        : "r"(a0), "r"(a1), "r"(a2), "r"(a3), "r"(b0), "r"(b1));
}

__device__ __forceinline__ void ldsm_x4(uint32_t r[4], uint32_t addr) {
    asm volatile(
        "ldmatrix.sync.aligned.m8n8.x4.shared.b16 {%0,%1,%2,%3}, [%4];"
        : "=r"(r[0]), "=r"(r[1]), "=r"(r[2]), "=r"(r[3]) : "r"(addr));
}

// ---------------------------------------------------------------------------
// K2: HMMA GEMM via smem + ldmatrix: out[r] = y[r] @ W^T + beta[r]*b
// 4 k-phases of 32 -> smem 20.5 KB -> 2 blocks/SM co-resident (sync overlap).
// Block = 256 thr (8 warps) -> 128 rows x 128 cols; warp = 32 rows x 64 cols.
// Tail: zero g_deg for the next graph replay's prep_kernel.
// ---------------------------------------------------------------------------
__global__ void __launch_bounds__(256)
gemm_mma_kernel(const float* __restrict__ bvec, float* __restrict__ out, int n) {
    __shared__ __half Wsm[DIM * SPAD];   // 10240 B
    __shared__ __half Ysm[DIM * SPAD];   // 10240 B

    int tid   = threadIdx.x;
    int wid   = tid >> 5;
    int lane  = tid & 31;
    int warpM = wid & 3;               // 4 M-slices of 32 rows
    int warpN = wid >> 2;              // 2 N-slices of 64 cols
    int row0  = blockIdx.x * TILE_M;
    int g     = lane >> 2;
    int i2    = (lane & 3) * 2;

    int grp = lane >> 3;
    int lr  = lane & 7;
    int ro  = (grp & 1) * 8 + lr;
    int co  = (grp >> 1) * 8;

    uint32_t ybase = smem_u32(Ysm);
    uint32_t wbase = smem_u32(Wsm);

    float c[2][8][4];
#pragma unroll
    for (int mt = 0; mt < 2; mt++)
#pragma unroll
        for (int nt = 0; nt < 8; nt++)
#pragma unroll
            for (int q = 0; q < 4; q++) c[mt][nt][q] = 0.f;

#pragma unroll
    for (int p = 0; p < 4; p++) {
        int kb0 = p * 32;
        __syncthreads();
        // Stage W[.][kb0..kb0+32) and y[row0+.][kb0..kb0+32): 512 uint4 each
#pragma unroll
        for (int it = 0; it < 2; it++) {
            int idx = tid + it * 256;
            int row = idx >> 2;
            int ch  = (idx & 3) * 8;
            *(uint4*)&Wsm[row * SPAD + ch] =
                *(const uint4*)(g_Wh + row * DIM + kb0 + ch);
            *(uint4*)&Ysm[row * SPAD + ch] =
                *(const uint4*)(g_yh + (size_t)(row0 + row) * DIM + kb0 + ch);
        }
        __syncthreads();

#pragma unroll
        for (int k = 0; k < 2; k++) {
            int kc = k * 16 + co;

            uint32_t a[2][4];
#pragma unroll
            for (int mt = 0; mt < 2; mt++) {
                uint32_t addr = ybase +
                    ((warpM * 32 + mt * 16 + ro) * SPAD + kc) * 2;
                ldsm_x4(a[mt], addr);
            }

#pragma unroll
            for (int ntp = 0; ntp < 4; ntp++) {
                uint32_t bfr[4];
                uint32_t addr = wbase +
                    ((warpN * 64 + ntp * 16 + ro) * SPAD + kc) * 2;
                ldsm_x4(bfr, addr);
#pragma unroll
                for (int mt = 0; mt < 2; mt++) {
                    mma16816(c[mt][ntp * 2 + 0], a[mt][0], a[mt][1], a[mt][2], a[mt][3],
                             bfr[0], bfr[2]);
                    mma16816(c[mt][ntp * 2 + 1], a[mt][0], a[mt][1], a[mt][2], a[mt][3],
                             bfr[1], bfr[3]);
                }
            }
        }
    }

    // Epilogue: c0,c1 -> row g cols i2..i2+1; c2,c3 -> row g+8.
    int n0 = warpN * 64;
#pragma unroll
    for (int mt = 0; mt < 2; mt++) {
        int r0 = row0 + warpM * 32 + mt * 16 + g;
        int r1 = r0 + 8;
        float be0 = (r0 < n) ? g_beta[r0] : 0.f;
        float be1 = (r1 < n) ? g_beta[r1] : 0.f;
#pragma unroll
        for (int nt = 0; nt < 8; nt++) {
            int col = n0 + nt * 8 + i2;
            float2 bv = *(const float2*)(bvec + col);
            if (r0 < n) {
                *(float2*)(out + (size_t)r0 * DIM + col) =
                    make_float2(c[mt][nt][0] + be0 * bv.x,
                                c[mt][nt][1] + be0 * bv.y);
            }
            if (r1 < n) {
                *(float2*)(out + (size_t)r1 * DIM + col) =
                    make_float2(c[mt][nt][2] + be1 * bv.x,
                                c[mt][nt][3] + be1 * bv.y);
            }
        }
    }

    // Tail: zero g_deg for the next replay (gemm never reads g_deg; grid has
    // 782*256 = 200k threads >= n). First call relies on static zero-init.
    int z = blockIdx.x * 256 + tid;
    if (z < n) g_deg[z] = 0;
}

// ---------------------------------------------------------------------------
// Launch (3 kernels: prep -> agg -> gemm)
// ---------------------------------------------------------------------------
extern "C" void kernel_launch(void* const* d_in, const int* in_sizes, int n_in,
                              void* d_out, int out_size) {
    const float* x   = (const float*)d_in[0];
    const int*   ei  = (const int*)d_in[1];
    const float* W   = (const float*)d_in[2];
    const float* b   = (const float*)d_in[3];
    float*       out = (float*)d_out;

    int n = in_sizes[0] / DIM;
    int e = in_sizes[1] / 2;

    int convBlocks = (int)(((size_t)n * (DIM / 2) + 255) / 256);
    int fillBlocks = (e + 255) / 256;
    prep_kernel<<<convBlocks + fillBlocks, 256>>>(x, W, ei, n, e, convBlocks);
    agg_kernel<<<((n * 32) + 255) / 256, 256>>>(n);
    gemm_mma_kernel<<<(n + TILE_M - 1) / TILE_M, 256>>>(b, out, n);
}

// round 9
// speedup vs baseline: 1.1376x; 1.1376x over previous
#include <cuda_runtime.h>
#include <cuda_fp16.h>
#include <cstdint>

#define DIM     128
#define NMAX    100000
#define MAXDEG  128
#define TILE_M  128
#define SPAD    72          // smem row stride in halfs (64 data + 8 pad = 144B)

// ---------------------------------------------------------------------------
// Scratch (allocation-free rule: module-scope device arrays)
// ---------------------------------------------------------------------------
__device__ int    g_deg[NMAX];
__device__ int    g_bucket[(size_t)NMAX * MAXDEG];     // 51.2 MB
__device__ __half g_xh[(size_t)NMAX * DIM];            // 25.6 MB  x in fp16
__device__ __half g_yh[(size_t)(NMAX + TILE_M) * DIM]; // fp16 y (zero pad tail)
__device__ __half g_Wh[DIM * DIM];                     // W in fp16
__device__ float  g_beta[NMAX];

__device__ __forceinline__ uint32_t smem_u32(const void* p) {
    uint32_t a;
    asm("{ .reg .u64 t; cvta.to.shared.u64 t, %1; cvt.u32.u64 %0, t; }"
        : "=r"(a) : "l"(p));
    return a;
}

__device__ __forceinline__ uint4 cvt8_f32_to_h16(float4 v0, float4 v1) {
    uint4 o;
    __half2 h;
    h = __float22half2_rn(make_float2(v0.x, v0.y)); o.x = *(const uint32_t*)&h;
    h = __float22half2_rn(make_float2(v0.z, v0.w)); o.y = *(const uint32_t*)&h;
    h = __float22half2_rn(make_float2(v1.x, v1.y)); o.z = *(const uint32_t*)&h;
    h = __float22half2_rn(make_float2(v1.z, v1.w)); o.w = *(const uint32_t*)&h;
    return o;
}

// ---------------------------------------------------------------------------
// K0: fused init — zero degrees + x->fp16 + W->fp16.
// Vectorized: 8 floats per thread (2x float4 load, 1x uint4 store) -> MLP=2,
// 4x fewer threads than the scalar version (which ran at 24% of HBM).
// ---------------------------------------------------------------------------
__global__ void init_kernel(const float* __restrict__ x,
                            const float* __restrict__ W, int n) {
    int i = blockIdx.x * blockDim.x + threadIdx.x;       // one per 8 floats
    size_t total8 = (size_t)n * (DIM / 8);               // 1.6M
    if ((size_t)i < total8) {
        const float4* p = (const float4*)x + (size_t)i * 2;
        ((uint4*)g_xh)[i] = cvt8_f32_to_h16(p[0], p[1]);
    }
    if (i < n) g_deg[i] = 0;
    if (i < DIM * DIM / 8) {
        const float4* p = (const float4*)W + (size_t)i * 2;
        ((uint4*)g_Wh)[i] = cvt8_f32_to_h16(p[0], p[1]);
    }
}

// ---------------------------------------------------------------------------
// K1: count degrees + scatter neighbor lists (edge_index delivered as int32)
// ---------------------------------------------------------------------------
__global__ void fill_kernel(const int* __restrict__ ei, int e, int n) {
    int i = blockIdx.x * blockDim.x + threadIdx.x;
    if (i >= e) return;
    int row = ei[i];
    int col = ei[(size_t)e + i];
    if ((unsigned)row >= (unsigned)n) return;
    if ((unsigned)col >= (unsigned)n) return;
    int slot = atomicAdd(&g_deg[row], 1);
    if (slot < MAXDEG) g_bucket[(size_t)row * MAXDEG + slot] = col;
}

// ---------------------------------------------------------------------------
// K2: warp-per-row aggregation (unchanged; near L2-gather roofline)
// y[r] = d_r * sum_c d_c * x[c] + d_r^2 * x[r];  beta[r] = d_r*sum d_c + d_r^2
// ---------------------------------------------------------------------------
__global__ void agg_kernel(int n) {
    int gw   = (blockIdx.x * blockDim.x + threadIdx.x) >> 5;
    int lane = threadIdx.x & 31;
    if (gw >= n) return;

    int degr = g_deg[gw];
    int degc = min(degr, MAXDEG);
    int half = lane >> 4;
    int li   = lane & 15;

    float acc[8];
#pragma unroll
    for (int t = 0; t < 8; t++) acc[t] = 0.f;
    float s = 0.f;

    for (int base = 0; base < degc; base += 32) {
        int m = min(32, degc - base);
        int   c  = 0;
        float dc = 0.f;
        if (lane < m) {
            c  = g_bucket[(size_t)gw * MAXDEG + base + lane];
            dc = rsqrtf((float)max(g_deg[c], 1));
        }
#pragma unroll 4
        for (int j = 0; j < m; j += 2) {
            int idx = j + half;
            int   cj  = __shfl_sync(0xffffffffu, c, idx);
            float dcj = __shfl_sync(0xffffffffu, dc, idx);
            uint4 v = *(const uint4*)(g_xh + (size_t)cj * DIM + li * 8);
            const __half2* hp = (const __half2*)&v;
#pragma unroll
            for (int t = 0; t < 4; t++) {
                float2 f = __half22float2(hp[t]);
                acc[t * 2 + 0] += dcj * f.x;
                acc[t * 2 + 1] += dcj * f.y;
            }
            s += dcj;
        }
    }

#pragma unroll
    for (int t = 0; t < 8; t++)
        acc[t] += __shfl_down_sync(0xffffffffu, acc[t], 16);
    s += __shfl_down_sync(0xffffffffu, s, 16);

    float dr = rsqrtf((float)max(degr, 1));
    float d2 = dr * dr;

    if (lane < 16) {
        uint4 xv = *(const uint4*)(g_xh + (size_t)gw * DIM + li * 8);
        const __half2* xp = (const __half2*)&xv;
        uint4 yo;
        uint32_t* yw = (uint32_t*)&yo;
#pragma unroll
        for (int t = 0; t < 4; t++) {
            float2 xf = __half22float2(xp[t]);
            __half2 p = __float22half2_rn(
                make_float2(dr * acc[t * 2 + 0] + d2 * xf.x,
                            dr * acc[t * 2 + 1] + d2 * xf.y));
            yw[t] = *(const uint32_t*)&p;
        }
        *(uint4*)(g_yh + (size_t)gw * DIM + li * 8) = yo;
    }
    if (lane == 0) g_beta[gw] = dr * s + d2;
}

// ---------------------------------------------------------------------------
// mma.sync m16n8k16 fp16 -> fp32
// ---------------------------------------------------------------------------
__device__ __forceinline__ void mma16816(float c[4],
                                         uint32_t a0, uint32_t a1,
                                         uint32_t a2, uint32_t a3,
                                         uint32_t b0, uint32_t b1) {
    asm volatile(
        "mma.sync.aligned.m16n8k16.row.col.f32.f16.f16.f32 "
        "{%0,%1,%2,%3}, {%4,%5,%6,%7}, {%8,%9}, {%0,%1,%2,%3};"
        : "+f"(c[0]), "+f"(c[1]), "+f"(c[2]), "+f"(c[3])
        : "r"(a0), "r"(a1), "r"(a2), "r"(a3), "r"(b0), "r"(b1));
}

__device__ __forceinline__ void ldsm_x4(uint32_t r[4], uint32_t addr) {
    asm volatile(
        "ldmatrix.sync.aligned.m8n8.x4.shared.b16 {%0,%1,%2,%3}, [%4];"
        : "=r"(r[0]), "=r"(r[1]), "=r"(r[2]), "=r"(r[3]) : "r"(addr));
}

// ---------------------------------------------------------------------------
// K3: HMMA GEMM via smem + ldmatrix (R7 proven version, 2 k-phases of 64)
// ---------------------------------------------------------------------------
__global__ void __launch_bounds__(256)
gemm_mma_kernel(const float* __restrict__ bvec, float* __restrict__ out, int n) {
    __shared__ __half Wsm[DIM * SPAD];   // 18432 B
    __shared__ __half Ysm[DIM * SPAD];   // 18432 B

    int tid   = threadIdx.x;
    int wid   = tid >> 5;
    int lane  = tid & 31;
    int warpM = wid & 3;
    int warpN = wid >> 2;
    int row0  = blockIdx.x * TILE_M;
    int g     = lane >> 2;
    int i2    = (lane & 3) * 2;

    int grp = lane >> 3;
    int lr  = lane & 7;
    int ro  = (grp & 1) * 8 + lr;
    int co  = (grp >> 1) * 8;

    uint32_t ybase = smem_u32(Ysm);
    uint32_t wbase = smem_u32(Wsm);

    float c[2][8][4];
#pragma unroll
    for (int mt = 0; mt < 2; mt++)
#pragma unroll
        for (int nt = 0; nt < 8; nt++)
#pragma unroll
            for (int q = 0; q < 4; q++) c[mt][nt][q] = 0.f;

#pragma unroll
    for (int p = 0; p < 2; p++) {
        int kb0 = p * 64;
        __syncthreads();
#pragma unroll
        for (int it = 0; it < 4; it++) {
            int idx = tid + it * 256;
            int row = idx >> 3;
            int ch  = (idx & 7) * 8;
            *(uint4*)&Wsm[row * SPAD + ch] =
                *(const uint4*)(g_Wh + row * DIM + kb0 + ch);
            *(uint4*)&Ysm[row * SPAD + ch] =
                *(const uint4*)(g_yh + (size_t)(row0 + row) * DIM + kb0 + ch);
        }
        __syncthreads();

#pragma unroll
        for (int k = 0; k < 4; k++) {
            int kc = k * 16 + co;

            uint32_t a[2][4];
#pragma unroll
            for (int mt = 0; mt < 2; mt++) {
                uint32_t addr = ybase +
                    ((warpM * 32 + mt * 16 + ro) * SPAD + kc) * 2;
                ldsm_x4(a[mt], addr);
            }

#pragma unroll
            for (int ntp = 0; ntp < 4; ntp++) {
                uint32_t bfr[4];
                uint32_t addr = wbase +
                    ((warpN * 64 + ntp * 16 + ro) * SPAD + kc) * 2;
                ldsm_x4(bfr, addr);
#pragma unroll
                for (int mt = 0; mt < 2; mt++) {
                    mma16816(c[mt][ntp * 2 + 0], a[mt][0], a[mt][1], a[mt][2], a[mt][3],
                             bfr[0], bfr[2]);
                    mma16816(c[mt][ntp * 2 + 1], a[mt][0], a[mt][1], a[mt][2], a[mt][3],
                             bfr[1], bfr[3]);
                }
            }
        }
    }

    int n0 = warpN * 64;
#pragma unroll
    for (int mt = 0; mt < 2; mt++) {
        int r0 = row0 + warpM * 32 + mt * 16 + g;
        int r1 = r0 + 8;
        float be0 = (r0 < n) ? g_beta[r0] : 0.f;
        float be1 = (r1 < n) ? g_beta[r1] : 0.f;
#pragma unroll
        for (int nt = 0; nt < 8; nt++) {
            int col = n0 + nt * 8 + i2;
            float2 bv = *(const float2*)(bvec + col);
            if (r0 < n) {
                *(float2*)(out + (size_t)r0 * DIM + col) =
                    make_float2(c[mt][nt][0] + be0 * bv.x,
                                c[mt][nt][1] + be0 * bv.y);
            }
            if (r1 < n) {
                *(float2*)(out + (size_t)r1 * DIM + col) =
                    make_float2(c[mt][nt][2] + be1 * bv.x,
                                c[mt][nt][3] + be1 * bv.y);
            }
        }
    }
}

// ---------------------------------------------------------------------------
// Launch
// ---------------------------------------------------------------------------
extern "C" void kernel_launch(void* const* d_in, const int* in_sizes, int n_in,
                              void* d_out, int out_size) {
    const float* x   = (const float*)d_in[0];
    const int*   ei  = (const int*)d_in[1];
    const float* W   = (const float*)d_in[2];
    const float* b   = (const float*)d_in[3];
    float*       out = (float*)d_out;

    int n = in_sizes[0] / DIM;
    int e = in_sizes[1] / 2;

    size_t init_tot = (size_t)n * (DIM / 8);   // threads (8 floats each)
    init_kernel<<<(int)((init_tot + 255) / 256), 256>>>(x, W, n);
    fill_kernel<<<(e + 255) / 256, 256>>>(ei, e, n);
    agg_kernel<<<((n * 32) + 255) / 256, 256>>>(n);
    gemm_mma_kernel<<<(n + TILE_M - 1) / TILE_M, 256>>>(b, out, n);
}